// round 2
// baseline (speedup 1.0000x reference)
#include <cuda_runtime.h>
#include <cstdint>

// Problem constants
constexpr int BB = 32;       // batch
constexpr int TT = 2048;     // time steps

// ---------------- scratch (static device globals; no allocation allowed) ----
__device__ float g_xg[(size_t)BB * TT * 3072];     // input-gate projections, max 3H=3072
__device__ float g_act0[(size_t)BB * TT * 1024];   // activation ping
__device__ float g_act1[(size_t)BB * TT * 1024];   // activation pong
__device__ float g_h[2 * 32 * 1024];               // hidden state, double buffered, layout f4[k>>2][b][k&3]
__device__ unsigned g_cnt;                          // grid barrier counter
__device__ unsigned g_gen;                          // grid barrier generation

// ---------------- packed f32x2 helpers (sm_100+) ---------------------------
__device__ __forceinline__ void fma2(unsigned long long& a, unsigned long long x, unsigned long long y) {
    asm("fma.rn.f32x2 %0, %1, %2, %0;" : "+l"(a) : "l"(x), "l"(y));
}
__device__ __forceinline__ unsigned long long pk2(float x, float y) {
    unsigned long long r; asm("mov.b64 %0, {%1,%2};" : "=l"(r) : "f"(x), "f"(y)); return r;
}
__device__ __forceinline__ float2 up2(unsigned long long v) {
    float2 f; asm("mov.b64 {%0,%1}, %2;" : "=f"(f.x), "=f"(f.y) : "l"(v)); return f;
}

// ---------------- input projection GEMM -------------------------------------
// C[m, n] = sum_k A[m, k] * W[n, k] + bias[n],  m = b*TT + t
// A element address = A + b*sb + t*st + k*sk   (handles both [B,C,T] and [B,T,C])
// Tile: BM=128, BN=64, BK=16; 256 threads; per-thread 8x4 via f32x2 row pairs.
__global__ __launch_bounds__(256) void gemm_xg(
    const float* __restrict__ A, const float* __restrict__ W,
    const float* __restrict__ bias, float* __restrict__ C,
    int K, int N3, long sb, long st, long sk)
{
    __shared__ __align__(16) float As[16][128];
    __shared__ __align__(16) float Bs[16][64];

    int tid = threadIdx.x;
    int n0 = blockIdx.x * 64;
    int m0 = blockIdx.y * 128;
    int bidx = m0 / TT;
    int t0 = m0 % TT;          // TT % 128 == 0 so tile stays within one batch row
    const float* Ab = A + (size_t)bidx * sb + (size_t)t0 * st;
    int tx = tid & 15, ty = tid >> 4;

    unsigned long long acc2[4][4];
#pragma unroll
    for (int i = 0; i < 4; ++i)
#pragma unroll
        for (int j = 0; j < 4; ++j) acc2[i][j] = 0ull;

    for (int k0 = 0; k0 < K; k0 += 16) {
        if (sk == 1) {
            // k contiguous (layers 1-3): each thread loads a float4 along k
#pragma unroll
            for (int i = 0; i < 2; ++i) {
                int lin = tid + i * 256;
                int m = lin >> 2, k4 = (lin & 3) * 4;
                const float* p = Ab + (size_t)m * st + (k0 + k4);
                float4 v = *(const float4*)p;
                As[k4 + 0][m] = v.x; As[k4 + 1][m] = v.y;
                As[k4 + 2][m] = v.z; As[k4 + 3][m] = v.w;
            }
        } else {
            // t contiguous (layer 0, x is [B,C,T]): float4 along m
#pragma unroll
            for (int i = 0; i < 2; ++i) {
                int lin = tid + i * 256;
                int k = lin >> 5, m4 = (lin & 31) * 4;
                const float* p = Ab + m4 + (size_t)(k0 + k) * sk;
                *(float4*)&As[k][m4] = *(const float4*)p;
            }
        }
        {
            int n = tid >> 2, k4 = (tid & 3) * 4;
            float4 v = *(const float4*)&W[(size_t)(n0 + n) * K + k0 + k4];
            Bs[k4 + 0][n] = v.x; Bs[k4 + 1][n] = v.y;
            Bs[k4 + 2][n] = v.z; Bs[k4 + 3][n] = v.w;
        }
        __syncthreads();

#pragma unroll
        for (int k = 0; k < 16; ++k) {
            const ulonglong2* ap = (const ulonglong2*)&As[k][ty * 8];
            ulonglong2 A0 = ap[0], A1 = ap[1];
            unsigned long long am[4] = {A0.x, A0.y, A1.x, A1.y};
            float4 bv = *(const float4*)&Bs[k][tx * 4];
            unsigned long long bd[4] = {pk2(bv.x, bv.x), pk2(bv.y, bv.y),
                                        pk2(bv.z, bv.z), pk2(bv.w, bv.w)};
#pragma unroll
            for (int mp = 0; mp < 4; ++mp)
#pragma unroll
                for (int j = 0; j < 4; ++j) fma2(acc2[mp][j], am[mp], bd[j]);
        }
        __syncthreads();
    }

    float4 bv = *(const float4*)&bias[n0 + tx * 4];
#pragma unroll
    for (int mp = 0; mp < 4; ++mp) {
        float2 c0 = up2(acc2[mp][0]), c1 = up2(acc2[mp][1]);
        float2 c2 = up2(acc2[mp][2]), c3 = up2(acc2[mp][3]);
        size_t r0 = (size_t)(m0 + ty * 8 + 2 * mp) * N3 + n0 + tx * 4;
        float4 o0 = {c0.x + bv.x, c1.x + bv.y, c2.x + bv.z, c3.x + bv.w};
        float4 o1 = {c0.y + bv.x, c1.y + bv.y, c2.y + bv.z, c3.y + bv.w};
        *(float4*)&C[r0] = o0;
        *(float4*)&C[r0 + N3] = o1;
    }
}

// ---------------- zero hidden state ----------------------------------------
__global__ void zero_h_kernel() {
    int i = blockIdx.x * blockDim.x + threadIdx.x;
    if (i < 2 * 32 * 1024) g_h[i] = 0.f;
}

// ---------------- persistent GRU recurrence --------------------------------
// Grid = 128 CTAs; CTA owns HC hidden indices (all 3 gates -> 3*HC rows of w_hh
// kept in SMEM). Each step: stage h[K][B] (f4 layout) to SMEM, 8 warps split K
// 8-ways, each warp accumulates all 3*HC rows with f32x2 FMAs, reduce via SMEM,
// apply gates, write h_new + output, then custom grid barrier.
template<int HC>
__global__ __launch_bounds__(256) void recur_kernel(
    const float* __restrict__ xg, const float* __restrict__ w_hh,
    const float* __restrict__ b_hh, float* __restrict__ out,
    int H, long os_b, long os_t, long os_j)
{
    extern __shared__ float smem[];
    const int K = H;
    const int NR = 3 * HC;
    float* w_s = smem;             // [NR][K]
    float* h_s = smem + NR * K;    // [K*32] floats; also aliased as reduction buffer

    int tid = threadIdx.x;
    int cta = blockIdx.x;
    int G = gridDim.x;
    int j0 = cta * HC;

    // load this CTA's w_hh rows into SMEM (rows: gate*H + j0 + jl)
    for (int r = 0; r < NR; ++r) {
        int gate = r / HC, jl = r % HC;
        const float* src = w_hh + (size_t)(gate * H + j0 + jl) * K;
        for (int k = tid * 4; k < K; k += 1024)
            *(float4*)&w_s[r * K + k] = *(const float4*)&src[k];
    }
    unsigned local_gen = 0;
    if (tid == 0) local_gen = *(volatile unsigned*)&g_gen;
    __syncthreads();

    int warp = tid >> 5, lane = tid & 31;
    int k4n = K >> 5;           // float4-iterations per warp (K/4/8)
    int k4b = warp * k4n;
    int ejl = tid >> 5, eb = tid & 31;
    const int nh4 = K * 8;      // float4 count of h buffer

    for (int t = 0; t < TT; ++t) {
        int p = t & 1;
        const float4* hsrc = (const float4*)&g_h[p * 32 * 1024];
        float4* hs4 = (float4*)h_s;
        for (int i = tid; i < nh4; i += 256) hs4[i] = hsrc[i];
        __syncthreads();

        unsigned long long acc2[NR];
#pragma unroll
        for (int r = 0; r < NR; ++r) acc2[r] = 0ull;

        const ulonglong2* hp = (const ulonglong2*)h_s;
        for (int k4 = k4b; k4 < k4b + k4n; ++k4) {
            ulonglong2 hv = hp[k4 * 32 + lane];   // h[4k..4k+3][b=lane]
#pragma unroll
            for (int r = 0; r < NR; ++r) {
                ulonglong2 wv = *(const ulonglong2*)&w_s[r * K + k4 * 4];
                fma2(acc2[r], hv.x, wv.x);
                fma2(acc2[r], hv.y, wv.y);
            }
        }
        __syncthreads();                 // h_s reads done; safe to alias as reduction buf
        float* red = h_s;
#pragma unroll
        for (int r = 0; r < NR; ++r) {
            float2 f = up2(acc2[r]);
            red[(warp * NR + r) * 32 + lane] = f.x + f.y;
        }
        __syncthreads();

        if (tid < HC * 32) {
            int jg = j0 + ejl;
            float s[3];
#pragma unroll
            for (int gate = 0; gate < 3; ++gate) {
                float v = b_hh[gate * H + jg];
#pragma unroll
                for (int w = 0; w < 8; ++w)
                    v += red[(w * NR + gate * HC + ejl) * 32 + eb];
                s[gate] = v;
            }
            const float* xgp = xg + ((size_t)eb * TT + t) * (3 * H);
            float xr = xgp[jg], xz = xgp[H + jg], xn = xgp[2 * H + jg];
            float r_ = 1.f / (1.f + __expf(-(xr + s[0])));
            float z_ = 1.f / (1.f + __expf(-(xz + s[1])));
            float n_ = tanhf(xn + r_ * s[2]);
            int hidx = (jg >> 2) * 128 + eb * 4 + (jg & 3);
            float hprev = g_h[p * 32 * 1024 + hidx];
            float hnew = (1.f - z_) * n_ + z_ * hprev;
            g_h[(p ^ 1) * 32 * 1024 + hidx] = hnew;
            out[(size_t)eb * os_b + (size_t)t * os_t + (size_t)jg * os_j] = hnew;
        }

        // ---- grid-wide barrier (sense via generation counter) ----
        __syncthreads();
        if (tid == 0) {
            __threadfence();
            unsigned a = atomicAdd(&g_cnt, 1);
            if (a == (unsigned)G - 1) {
                g_cnt = 0;
                __threadfence();
                atomicAdd(&g_gen, 1);
            } else {
                while (*(volatile unsigned*)&g_gen == local_gen) { }
            }
            local_gen++;
            __threadfence();
        }
        __syncthreads();
    }
}

extern "C" void kernel_launch(void* const* d_in, const int* in_sizes, int n_in,
                              void* d_out, int out_size) {
    const float* x = (const float*)d_in[0];
    const float* wih[4]; const float* whh[4]; const float* bih[4]; const float* bhh[4];
    for (int l = 0; l < 4; ++l) {
        wih[l] = (const float*)d_in[1 + 4 * l];
        whh[l] = (const float*)d_in[2 + 4 * l];
        bih[l] = (const float*)d_in[3 + 4 * l];
        bhh[l] = (const float*)d_in[4 + 4 * l];
    }
    float *xg, *a0, *a1;
    cudaGetSymbolAddress((void**)&xg, g_xg);
    cudaGetSymbolAddress((void**)&a0, g_act0);
    cudaGetSymbolAddress((void**)&a1, g_act1);
    float* dout = (float*)d_out;

    const int SMEM4 = (3 * 4 * 512 + 512 * 32) * 4;     // 90112 B
    const int SMEM8 = (3 * 8 * 1024 + 1024 * 32) * 4;   // 229376 B
    cudaFuncSetAttribute(recur_kernel<4>, cudaFuncAttributeMaxDynamicSharedMemorySize, SMEM4);
    cudaFuncSetAttribute(recur_kernel<8>, cudaFuncAttributeMaxDynamicSharedMemorySize, SMEM8);

    struct Cfg { const float* A; int K; int H; long sb, st, sk; float* out; long ob, ot, oj; };
    Cfg cfg[4] = {
        { x,   256,  512, (long)256 * 2048,  1,    2048, a0,   (long)2048 * 512,  512,  1    },
        { a0,  512,  512, (long)2048 * 512,  512,  1,    a1,   (long)2048 * 512,  512,  1    },
        { a1,  512, 1024, (long)2048 * 512,  512,  1,    a0,   (long)2048 * 1024, 1024, 1    },
        { a0, 1024, 1024, (long)2048 * 1024, 1024, 1,    dout, (long)1024 * 2048, 1,    2048 },
    };

    for (int l = 0; l < 4; ++l) {
        int N3 = 3 * cfg[l].H;
        dim3 gg(N3 / 64, (BB * TT) / 128);
        gemm_xg<<<gg, 256>>>(cfg[l].A, wih[l], bih[l], xg,
                             cfg[l].K, N3, cfg[l].sb, cfg[l].st, cfg[l].sk);
        zero_h_kernel<<<64, 1024>>>();
        if (cfg[l].H == 512)
            recur_kernel<4><<<128, 256, SMEM4>>>(xg, whh[l], bhh[l], cfg[l].out,
                                                 512, cfg[l].ob, cfg[l].ot, cfg[l].oj);
        else
            recur_kernel<8><<<128, 256, SMEM8>>>(xg, whh[l], bhh[l], cfg[l].out,
                                                 1024, cfg[l].ob, cfg[l].ot, cfg[l].oj);
    }
}